// round 16
// baseline (speedup 1.0000x reference)
#include <cuda_runtime.h>
#include <cuda_fp16.h>
#include <cstdint>

// Linear RNN h_t = x_t@W + h_{t-1}@R via log-doubling scan, HMMA mma.sync fp16
// hi/lo-split core, fp32 accum. Persistent flag-chained scan; all big GEMMs
// 1-pass; power chain on a forked stream.
// R15: join moved AFTER level 1 (L1 + h0 fold need only PT(0), computed
// pre-fork) -> power chain fully hidden, so it returns to 3-pass precision.

#define UD 1024
#define BT 32768

// hi/lo contiguous: lo part lives at a fixed element offset from hi
#define LO_STATE 33554432
#define LO_X     16777216
#define LO_H0    32768
#define LO_P     1048576
#define LO_W     524288

__device__ __half g_s0[67108864];     // state ping [hi|lo]
__device__ __half g_s1[67108864];     // state pong [hi|lo]
__device__ __half g_x [33554432];     // x time-major [hi|lo]
__device__ __half g_h0[65536];        // h0 [hi|lo]
__device__ __half g_wt[1048576];      // W^T K-major [hi|lo]
__device__ __half g_p [5][2097152];   // R^(2^l) row-major [hi|lo]
__device__ __half g_pt[5][2097152];   // (R^T)^(2^l) K-major [hi|lo]
__device__ __half g_p32t[2097152];    // (R^T)^32 for the scan [hi|lo]
__device__ unsigned int g_done[256];  // [chunk s][rowTile] completion counters

// ---------------- helpers ----------------
__device__ __forceinline__ uint32_t smem_u32(const void* p) {
    uint32_t a;
    asm("{ .reg .u64 t; cvta.to.shared.u64 t, %1; cvt.u32.u64 %0, t; }"
        : "=r"(a) : "l"(p));
    return a;
}
__device__ __forceinline__ void cpa16(uint32_t d, const void* s) {
    asm volatile("cp.async.cg.shared.global [%0], [%1], 16;" :: "r"(d), "l"(s) : "memory");
}
#define CPA_COMMIT() asm volatile("cp.async.commit_group;" ::: "memory")

__device__ __forceinline__ uint32_t pk(__half a, __half b) {
    return (uint32_t)__half_as_ushort(a) | ((uint32_t)__half_as_ushort(b) << 16);
}
__device__ __forceinline__ void split4(float4 v, uint2& h, uint2& l) {
    __half h0 = __float2half(v.x), h1 = __float2half(v.y);
    __half h2 = __float2half(v.z), h3 = __float2half(v.w);
    __half l0 = __float2half(v.x - __half2float(h0));
    __half l1 = __float2half(v.y - __half2float(h1));
    __half l2 = __float2half(v.z - __half2float(h2));
    __half l3 = __float2half(v.w - __half2float(h3));
    h.x = pk(h0, h1); h.y = pk(h2, h3);
    l.x = pk(l0, l1); l.y = pk(l2, l3);
}

#define LDSM4(r0, r1, r2, r3, ad) \
    asm volatile("ldmatrix.sync.aligned.m8n8.x4.shared.b16 {%0,%1,%2,%3}, [%4];" \
        : "=r"(r0), "=r"(r1), "=r"(r2), "=r"(r3) : "r"(ad))

#define MMA16816(acc, a, b) \
    asm volatile( \
        "mma.sync.aligned.m16n8k16.row.col.f32.f16.f16.f32 " \
        "{%0,%1,%2,%3}, {%4,%5,%6,%7}, {%8,%9}, {%0,%1,%2,%3};" \
        : "+f"((acc)[0]), "+f"((acc)[1]), "+f"((acc)[2]), "+f"((acc)[3]) \
        : "r"((a)[0]), "r"((a)[1]), "r"((a)[2]), "r"((a)[3]), \
          "r"((b)[0]), "r"((b)[1]))

// ======================= TM=128 / TN=32 GEMM (powers, h0 fold) ===============
// C[m,n] = sum_k A[m,k]*Bt[n,k] (Bt K-major [N,K]); nPass in {1,2,3}:
// pass 0: Ah*Bh, pass 1: Al*Bh, pass 2: Ah*Bl (fp32 accum).
// MODE 0: C = A@B     MODE 2: C[r] = S[r] + A[r]@B
template<int MODE>
__global__ void __launch_bounds__(256, 2) tgemm(
    const __half* __restrict__ A, int loA,
    const __half* __restrict__ Bm, int loB,
    const __half* __restrict__ S,
    __half* __restrict__ C, int loSC,
    int M, int Kd, int nPass)
{
    constexpr int TN = 32;
    constexpr int ABYTES = 128 * 128;
    constexpr int STG    = ABYTES + TN * 128;
    extern __shared__ char smem_[];

    const int tid  = threadIdx.x;
    const int wid  = tid >> 5, lane = tid & 31;
    const int rowTile = blockIdx.y * 128;
    const int colBase = blockIdx.x * TN;
    const int wr = wid >> 1, wc = wid & 1;
    constexpr int NN = 2;
    const int wcBase = wc * 16;

    const uint32_t sb = smem_u32(smem_);
    const int nk   = Kd >> 6;
    const int nSeg = nPass * nk;

    const __half* baseA[4];
    uint32_t aoffs[4];
    #pragma unroll
    for (int i = 0; i < 4; i++) {
        int t = tid + i * 256;
        int row = t >> 3, ch = t & 7;
        int r = rowTile + row;
        int ar = r < 0 ? 0 : (r > M - 1 ? M - 1 : r);
        baseA[i] = A + (size_t)ar * Kd + ch * 8;
        aoffs[i] = row * 128 + ((ch ^ (row & 7)) << 4);
    }
    const __half* baseB;
    uint32_t boffs;
    {
        int row = tid >> 3, ch = tid & 7;
        baseB = Bm + (size_t)(colBase + row) * Kd + ch * 8;
        boffs = ABYTES + row * 128 + ((ch ^ (row & 7)) << 4);
    }

    auto load_stage = [&](int buf, int seg) {
        int phase = (seg >= nk) + (seg >= 2 * nk);
        int koff  = (seg - phase * nk) * 64;
        int dA = koff + ((phase == 1) ? loA : 0);
        int dB = koff + ((phase == 2) ? loB : 0);
        const uint32_t stb = sb + buf * STG;
        #pragma unroll
        for (int i = 0; i < 4; i++) cpa16(stb + aoffs[i], baseA[i] + dA);
        cpa16(stb + boffs, baseB + dB);
    };

    const int sw = lane & 7;
    const uint32_t arow0 = (uint32_t)((wr * 32 + (lane & 15)) * 128);
    const int aunit = (lane >> 4);
    const uint32_t brow0 = (uint32_t)((wcBase + ((lane >> 4) << 3) + (lane & 7)) * 128);
    const int bunit = (lane >> 3) & 1;

    float acc[2][NN][4] = {};

    load_stage(0, 0); CPA_COMMIT();
    if (nSeg > 1) load_stage(1, 1);
    CPA_COMMIT();

    for (int s = 0; s < nSeg; s++) {
        asm volatile("cp.async.wait_group 1;" ::: "memory");
        __syncthreads();
        if (s + 2 < nSeg) load_stage((s + 2) % 3, s + 2);
        CPA_COMMIT();
        const uint32_t abase = sb + (s % 3) * STG;
        #pragma unroll
        for (int k16 = 0; k16 < 4; k16++) {
            uint32_t a[2][4], b[NN][2];
            #pragma unroll
            for (int mi = 0; mi < 2; mi++) {
                uint32_t ad = abase + arow0 + mi * (16 * 128)
                            + (((k16 * 2 + aunit) ^ sw) << 4);
                LDSM4(a[mi][0], a[mi][1], a[mi][2], a[mi][3], ad);
            }
            {
                uint32_t bd = abase + ABYTES + brow0
                            + (((k16 * 2 + bunit) ^ sw) << 4);
                LDSM4(b[0][0], b[0][1], b[1][0], b[1][1], bd);
            }
            #pragma unroll
            for (int mi = 0; mi < 2; mi++)
                #pragma unroll
                for (int nj = 0; nj < NN; nj++)
                    MMA16816(acc[mi][nj], a[mi], b[nj]);
        }
    }

    #pragma unroll
    for (int mi = 0; mi < 2; mi++) {
        #pragma unroll
        for (int half = 0; half < 2; half++) {
            int rr = rowTile + wr * 32 + mi * 16 + half * 8 + (lane >> 2);
            if (rr >= M) continue;
            const size_t rb = (size_t)rr * UD;
            #pragma unroll
            for (int nj = 0; nj < NN; nj++) {
                int col = colBase + wcBase + nj * 8 + (lane & 3) * 2;
                float v0 = acc[mi][nj][half * 2];
                float v1 = acc[mi][nj][half * 2 + 1];
                if (MODE == 2) {
                    __half2 sh2 = *(const __half2*)(S + rb + col);
                    __half2 sl2 = *(const __half2*)(S + loSC + rb + col);
                    float2 fh = __half22float2(sh2);
                    float2 fl = __half22float2(sl2);
                    v0 += fh.x + fl.x;
                    v1 += fh.y + fl.y;
                }
                __half h0_ = __float2half(v0), h1_ = __float2half(v1);
                __half l0_ = __float2half(v0 - __half2float(h0_));
                __half l1_ = __float2half(v1 - __half2float(h1_));
                *(uint32_t*)(C + rb + col)        = pk(h0_, h1_);
                *(uint32_t*)(C + loSC + rb + col) = pk(l0_, l1_);
            }
        }
    }
}

// ======================= TM=256 / TN=128 GEMM (xW + doubling levels) =========
// nPass in {1,2}: pass 0: Ah*Bh, pass 1: Al*Bh (B hi-only).
// MODE 0: C = A@B
// MODE 1: C[r] = S[r] + (r>=shift ? A[r-shift]@B : 0)
template<int MODE>
__global__ void __launch_bounds__(256, 1) tgemm2(
    const __half* __restrict__ A, int loA,
    const __half* __restrict__ Bm,
    const __half* __restrict__ S,
    __half* __restrict__ C, int loSC,
    int M, int Kd, int shift, int nPass)
{
    constexpr int ABYTES = 256 * 128;          // 256 rows x 64 fp16
    constexpr int BBYTES = 128 * 128;
    constexpr int STG    = ABYTES + BBYTES;
    extern __shared__ char smem_[];

    const int tid  = threadIdx.x;
    const int wid  = tid >> 5, lane = tid & 31;
    const int rowTile = blockIdx.y * 256;
    const int colBase = blockIdx.x * 128;
    const int wr = wid >> 1, wc = wid & 1;     // 4x2 warp grid: 64 rows x 64 cols

    const uint32_t sb = smem_u32(smem_);
    const int nk   = Kd >> 6;
    const int nSeg = nPass * nk;

    const __half* baseA[8];
    uint32_t aoffs[8];
    #pragma unroll
    for (int i = 0; i < 8; i++) {
        int t = tid + i * 256;
        int row = t >> 3, ch = t & 7;
        int r = rowTile + row;
        int ar = (MODE == 1) ? r - shift : r;
        ar = ar < 0 ? 0 : (ar > M - 1 ? M - 1 : ar);
        baseA[i] = A + (size_t)ar * Kd + ch * 8;
        aoffs[i] = row * 128 + ((ch ^ (row & 7)) << 4);
    }
    const __half* baseB[4];
    uint32_t boffs[4];
    #pragma unroll
    for (int i = 0; i < 4; i++) {
        int t = tid + i * 256;
        int row = t >> 3, ch = t & 7;
        baseB[i] = Bm + (size_t)(colBase + row) * Kd + ch * 8;
        boffs[i] = ABYTES + row * 128 + ((ch ^ (row & 7)) << 4);
    }

    auto load_stage = [&](int buf, int seg) {
        int phase = (seg >= nk) ? 1 : 0;
        int koff  = (seg - phase * nk) * 64;
        int dA = koff + (phase ? loA : 0);
        const uint32_t stb = sb + buf * STG;
        #pragma unroll
        for (int i = 0; i < 8; i++) cpa16(stb + aoffs[i], baseA[i] + dA);
        #pragma unroll
        for (int i = 0; i < 4; i++) cpa16(stb + boffs[i], baseB[i] + koff);
    };

    const int sw = lane & 7;
    const uint32_t arow0 = (uint32_t)((wr * 64 + (lane & 15)) * 128);
    const int aunit = (lane >> 4);
    const uint32_t brow0 = (uint32_t)((wc * 64 + ((lane >> 4) << 3) + (lane & 7)) * 128);
    const int bunit = (lane >> 3) & 1;

    float acc[4][8][4] = {};

    load_stage(0, 0); CPA_COMMIT();
    if (nSeg > 1) load_stage(1, 1);
    CPA_COMMIT();

    for (int s = 0; s < nSeg; s++) {
        asm volatile("cp.async.wait_group 1;" ::: "memory");
        __syncthreads();
        if (s + 2 < nSeg) load_stage((s + 2) % 3, s + 2);
        CPA_COMMIT();
        const uint32_t abase = sb + (s % 3) * STG;
        #pragma unroll
        for (int k16 = 0; k16 < 4; k16++) {
            uint32_t a[4][4], b[8][2];
            #pragma unroll
            for (int mi = 0; mi < 4; mi++) {
                uint32_t ad = abase + arow0 + mi * (16 * 128)
                            + (((k16 * 2 + aunit) ^ sw) << 4);
                LDSM4(a[mi][0], a[mi][1], a[mi][2], a[mi][3], ad);
            }
            #pragma unroll
            for (int bj = 0; bj < 4; bj++) {
                uint32_t bd = abase + ABYTES + brow0 + bj * (16 * 128)
                            + (((k16 * 2 + bunit) ^ sw) << 4);
                LDSM4(b[2 * bj][0], b[2 * bj][1], b[2 * bj + 1][0], b[2 * bj + 1][1], bd);
            }
            #pragma unroll
            for (int mi = 0; mi < 4; mi++)
                #pragma unroll
                for (int nj = 0; nj < 8; nj++)
                    MMA16816(acc[mi][nj], a[mi], b[nj]);
        }
    }

    #pragma unroll
    for (int mi = 0; mi < 4; mi++) {
        #pragma unroll
        for (int half = 0; half < 2; half++) {
            int rr = rowTile + wr * 64 + mi * 16 + half * 8 + (lane >> 2);
            if (rr >= M) continue;
            const bool live = (MODE != 1) || (rr >= shift);
            const size_t rb = (size_t)rr * UD;
            #pragma unroll
            for (int nj = 0; nj < 8; nj++) {
                int col = colBase + wc * 64 + nj * 8 + (lane & 3) * 2;
                float v0 = acc[mi][nj][half * 2];
                float v1 = acc[mi][nj][half * 2 + 1];
                if (MODE == 1) {
                    __half2 sh2 = *(const __half2*)(S + rb + col);
                    __half2 sl2 = *(const __half2*)(S + loSC + rb + col);
                    float2 fh = __half22float2(sh2);
                    float2 fl = __half22float2(sl2);
                    v0 = fh.x + fl.x + (live ? v0 : 0.f);
                    v1 = fh.y + fl.y + (live ? v1 : 0.f);
                }
                __half h0_ = __float2half(v0), h1_ = __float2half(v1);
                __half l0_ = __float2half(v0 - __half2float(h0_));
                __half l1_ = __float2half(v1 - __half2float(h1_));
                *(uint32_t*)(C + rb + col)        = pk(h0_, h1_);
                *(uint32_t*)(C + loSC + rb + col) = pk(l0_, l1_);
            }
        }
    }
}

// ======================= persistent flag-chained scan ========================
// ONE kernel for the whole 31-step sequential scan (1-pass fp16; product term
// gain(R^32)~0.07 of output). 256 CTAs = 8 rowTiles x 32 colTiles, all
// resident (occupancy 2, 296 slots). Per-rowTile release/acquire counters.
// Also performs the chunk-0 transposed fp32 copy to OUT.
__global__ void __launch_bounds__(256, 2) tscan(
    const __half* __restrict__ Bm,   // (R^T)^32, hi part at offset 0
    __half* __restrict__ ST,         // s1 base (hi; lo at +LO_STATE)
    float* __restrict__ OUT)
{
    constexpr int TN = 32;
    constexpr int ABYTES = 128 * 128;
    constexpr int STG    = ABYTES + TN * 128;
    extern __shared__ char smem_[];

    const int tid  = threadIdx.x;
    const int wid  = tid >> 5, lane = tid & 31;
    const int rtIdx = blockIdx.x >> 5;           // 0..7
    const int rowTile = rtIdx * 128;
    const int colBase = (blockIdx.x & 31) * TN;
    const int wr = wid >> 1, wc = wid & 1;
    constexpr int NN = 2;
    const int wcBase = wc * 16;
    const uint32_t sb = smem_u32(smem_);

    // ---- chunk 0 is already final: transposed fp32 copy to OUT ----
    {
        int r0 = tid >> 1;                       // 0..127
        int c0 = colBase + (tid & 1) * 16;
        int g  = rowTile + r0;
        size_t src = (size_t)g * UD + c0;
        float* op = OUT + (size_t)((g & 31) * 1024 + (g >> 5)) * UD + c0;
        #pragma unroll
        for (int i = 0; i < 16; i += 2) {
            __half2 h2 = *(const __half2*)(ST + src + i);
            __half2 l2 = *(const __half2*)(ST + LO_STATE + src + i);
            float2 fh = __half22float2(h2), fl = __half22float2(l2);
            op[i]     = fh.x + fl.x;
            op[i + 1] = fh.y + fl.y;
        }
    }

    // ---- constant addressing ----
    uint32_t aoffs[4]; int arowL[4], achL[4];
    #pragma unroll
    for (int i = 0; i < 4; i++) {
        int t = tid + i * 256;
        int row = t >> 3, ch = t & 7;
        arowL[i] = rowTile + row;
        achL[i]  = ch * 8;
        aoffs[i] = row * 128 + ((ch ^ (row & 7)) << 4);
    }
    const __half* baseB;
    uint32_t boffs;
    {
        int row = tid >> 3, ch = tid & 7;
        baseB = Bm + (size_t)(colBase + row) * UD + ch * 8;
        boffs = ABYTES + row * 128 + ((ch ^ (row & 7)) << 4);
    }
    const int sw = lane & 7;
    const uint32_t arow0 = (uint32_t)((wr * 32 + (lane & 15)) * 128);
    const int aunit = (lane >> 4);
    const uint32_t brow0 = (uint32_t)((wcBase + ((lane >> 4) << 3) + (lane & 7)) * 128);
    const int bunit = (lane >> 3) & 1;

    for (int s = 1; s < 32; s++) {
        const __half* A = ST + (size_t)(s - 1) * 1048576;
        __half* C = ST + (size_t)s * 1048576;

        // acquire: wait for the 32 CTAs that wrote our A rows of chunk s-1
        if (s >= 2) {
            if (tid == 0) {
                while (((volatile unsigned int*)g_done)[(s - 1) * 8 + rtIdx] < 32u) {}
                __threadfence();
            }
            __syncthreads();
        }

        auto load_stage = [&](int buf, int seg) {
            int koff = seg * 64;
            const uint32_t stb = sb + buf * STG;
            #pragma unroll
            for (int i = 0; i < 4; i++)
                cpa16(stb + aoffs[i], A + (size_t)arowL[i] * UD + achL[i] + koff);
            cpa16(stb + boffs, baseB + koff);
        };

        float acc[2][NN][4] = {};
        load_stage(0, 0); CPA_COMMIT();
        load_stage(1, 1); CPA_COMMIT();

        for (int seg = 0; seg < 16; seg++) {
            asm volatile("cp.async.wait_group 1;" ::: "memory");
            __syncthreads();
            if (seg + 2 < 16) load_stage((seg + 2) % 3, seg + 2);
            CPA_COMMIT();
            const uint32_t abase = sb + (seg % 3) * STG;
            #pragma unroll
            for (int k16 = 0; k16 < 4; k16++) {
                uint32_t a[2][4], b[NN][2];
                #pragma unroll
                for (int mi = 0; mi < 2; mi++) {
                    uint32_t ad = abase + arow0 + mi * (16 * 128)
                                + (((k16 * 2 + aunit) ^ sw) << 4);
                    LDSM4(a[mi][0], a[mi][1], a[mi][2], a[mi][3], ad);
                }
                {
                    uint32_t bd = abase + ABYTES + brow0
                                + (((k16 * 2 + bunit) ^ sw) << 4);
                    LDSM4(b[0][0], b[0][1], b[1][0], b[1][1], bd);
                }
                #pragma unroll
                for (int mi = 0; mi < 2; mi++)
                    #pragma unroll
                    for (int nj = 0; nj < NN; nj++)
                        MMA16816(acc[mi][nj], a[mi], b[nj]);
            }
        }

        // epilogue: C = S + acc (in place), dual fp32 transposed write to OUT
        const int rowOff = s * 1024;
        #pragma unroll
        for (int mi = 0; mi < 2; mi++) {
            #pragma unroll
            for (int half = 0; half < 2; half++) {
                int rr = rowTile + wr * 32 + mi * 16 + half * 8 + (lane >> 2);
                const size_t rb = (size_t)rr * UD;
                int g = rowOff + rr;
                float* op = OUT + (size_t)((g & 31) * 1024 + (g >> 5)) * UD;
                #pragma unroll
                for (int nj = 0; nj < NN; nj++) {
                    int col = colBase + wcBase + nj * 8 + (lane & 3) * 2;
                    float v0 = acc[mi][nj][half * 2];
                    float v1 = acc[mi][nj][half * 2 + 1];
                    __half2 sh2 = *(const __half2*)(C + rb + col);
                    __half2 sl2 = *(const __half2*)(C + LO_STATE + rb + col);
                    float2 fh = __half22float2(sh2);
                    float2 fl = __half22float2(sl2);
                    v0 += fh.x + fl.x;
                    v1 += fh.y + fl.y;
                    __half h0_ = __float2half(v0), h1_ = __float2half(v1);
                    __half l0_ = __float2half(v0 - __half2float(h0_));
                    __half l1_ = __float2half(v1 - __half2float(h1_));
                    *(uint32_t*)(C + rb + col)            = pk(h0_, h1_);
                    *(uint32_t*)(C + LO_STATE + rb + col) = pk(l0_, l1_);
                    op[col] = v0; op[col + 1] = v1;
                }
            }
        }

        // release: publish this CTA's tile of chunk s
        __threadfence();
        __syncthreads();
        if (tid == 0) atomicAdd(&g_done[s * 8 + rtIdx], 1u);
    }
}

__global__ void zero_done() { g_done[threadIdx.x] = 0u; }

// ======================= pre kernels =======================
__global__ void split_x(const float* __restrict__ x, __half* __restrict__ o)
{
    int id = blockIdx.x * 256 + threadIdx.x;
    int r = id >> 7;                                  // time-major row t*32+b
    int c = (id & 127) << 2;
    int b = r & 31, t = r >> 5;
    float4 vv = *(const float4*)(x + (size_t)(b * 1024 + t) * 512 + c);
    uint2 h, l; split4(vv, h, l);
    *(uint2*)(o + (size_t)r * 512 + c) = h;
    *(uint2*)(o + LO_X + (size_t)r * 512 + c) = l;
}

__global__ void split_plain(const float* __restrict__ in,
                            __half* __restrict__ o, int loOff)
{
    int id = blockIdx.x * 256 + threadIdx.x;
    float4 vv = *(const float4*)(in + (size_t)id * 4);
    uint2 h, l; split4(vv, h, l);
    *(uint2*)(o + (size_t)id * 4) = h;
    *(uint2*)(o + loOff + (size_t)id * 4) = l;
}

__global__ void tsplit(const float* __restrict__ in,
                       __half* __restrict__ o, int loOff, int K, int N)
{
    __shared__ float tile[32][33];
    int nb = blockIdx.x * 32, kb = blockIdx.y * 32;
    int tx = threadIdx.x, ty = threadIdx.y;
    #pragma unroll
    for (int j = 0; j < 32; j += 8)
        tile[ty + j][tx] = in[(size_t)(kb + ty + j) * N + nb + tx];
    __syncthreads();
    #pragma unroll
    for (int j = 0; j < 32; j += 8) {
        float vv = tile[tx][ty + j];
        size_t off = (size_t)(nb + ty + j) * K + kb + tx;
        __half h = __float2half(vv);
        o[off] = h;
        o[loOff + off] = __float2half(vv - __half2float(h));
    }
}

// exact hi/lo fp16 transpose: out[c][r] = in[r][c], 1024x1024, z in {0,1}
__global__ void ttrans(const __half* __restrict__ in, __half* __restrict__ out)
{
    __shared__ __half tile[32][33];
    const __half* ip = in  + (size_t)blockIdx.z * LO_P;
    __half* op       = out + (size_t)blockIdx.z * LO_P;
    int cb = blockIdx.x * 32, rb = blockIdx.y * 32;
    int tx = threadIdx.x, ty = threadIdx.y;
    #pragma unroll
    for (int j = 0; j < 32; j += 8)
        tile[ty + j][tx] = ip[(size_t)(rb + ty + j) * 1024 + cb + tx];
    __syncthreads();
    #pragma unroll
    for (int j = 0; j < 32; j += 8)
        op[(size_t)(cb + ty + j) * 1024 + rb + tx] = tile[tx][ty + j];
}

// ======================= host =======================
extern "C" void kernel_launch(void* const* d_in, const int* in_sizes, int n_in,
                              void* d_out, int out_size)
{
    const float* x  = (const float*)d_in[0];   // [32,1024,512]
    const float* h0 = (const float*)d_in[1];   // [32,1024]
    const float* W  = (const float*)d_in[2];   // [512,1024]
    const float* R  = (const float*)d_in[3];   // [1024,1024]
    float* out = (float*)d_out;                // [32,1024,1024]

    __half *s0, *s1, *xs, *h0s, *wt, *p, *pt, *p32t;
    cudaGetSymbolAddress((void**)&s0,  g_s0);
    cudaGetSymbolAddress((void**)&s1,  g_s1);
    cudaGetSymbolAddress((void**)&xs,  g_x);
    cudaGetSymbolAddress((void**)&h0s, g_h0);
    cudaGetSymbolAddress((void**)&wt,  g_wt);
    cudaGetSymbolAddress((void**)&p,   g_p);
    cudaGetSymbolAddress((void**)&pt,  g_pt);
    cudaGetSymbolAddress((void**)&p32t, g_p32t);

    auto P_  = [&](int i) { return p  + (size_t)i * 2097152; };
    auto PT_ = [&](int i) { return pt + (size_t)i * 2097152; };

    constexpr int DS32 = 3 * (128 + 32) * 128;    // 61440
    constexpr int DS2  = 3 * (256 + 128) * 128;   // 147456
    cudaFuncSetAttribute(tgemm<0>,  cudaFuncAttributeMaxDynamicSharedMemorySize, DS32);
    cudaFuncSetAttribute(tgemm<2>,  cudaFuncAttributeMaxDynamicSharedMemorySize, DS32);
    cudaFuncSetAttribute(tgemm2<0>, cudaFuncAttributeMaxDynamicSharedMemorySize, DS2);
    cudaFuncSetAttribute(tgemm2<1>, cudaFuncAttributeMaxDynamicSharedMemorySize, DS2);
    cudaFuncSetAttribute(tscan,     cudaFuncAttributeMaxDynamicSharedMemorySize, DS32);

    // forked stream + events (host-side objects only; fresh each call)
    cudaStream_t s2;
    cudaEvent_t evFork, evJoin;
    cudaStreamCreateWithFlags(&s2, cudaStreamNonBlocking);
    cudaEventCreateWithFlags(&evFork, cudaEventDisableTiming);
    cudaEventCreateWithFlags(&evJoin, cudaEventDisableTiming);

    dim3 blk(256);
    dim3 gPow(32, 8);    // 1024-row GEMMs, TM=128/TN=32
    dim3 gB2(8, 128);    // 32768-row GEMMs, TM=256/TN=128
    dim3 gT(32, 32, 2);  // hi/lo transpose
    dim3 bT(32, 8);

    // ---- shared prerequisites (main stream) ----
    split_plain<<<32, 256>>>(h0, h0s, LO_H0);
    split_plain<<<1024, 256>>>(R, P_(0), LO_P);
    tsplit<<<dim3(32, 32), dim3(32, 8)>>>(R, PT_(0), LO_P, 1024, 1024);

    // ---- fork: power chain (3-pass, fully hidden) on s2 ----
    cudaEventRecord(evFork, 0);
    cudaStreamWaitEvent(s2, evFork, 0);

    zero_done<<<1, 256, 0, s2>>>();
    for (int lv = 1; lv < 5; lv++) {
        tgemm<0><<<gPow, blk, DS32, s2>>>(P_(lv-1), LO_P, PT_(lv-1), LO_P,
                                          nullptr, P_(lv), LO_P,
                                          1024, 1024, 3);
        ttrans<<<gT, bT, 0, s2>>>(P_(lv), PT_(lv));
    }
    tgemm<0><<<gPow, blk, DS32, s2>>>(PT_(4), LO_P, P_(4), LO_P,
                                      nullptr, p32t, LO_P,
                                      1024, 1024, 3);
    cudaEventRecord(evJoin, s2);

    // main: x split + W split + b0 = x @ W (1-pass)
    split_x<<<16384, 256>>>(x, xs);
    tsplit<<<dim3(32, 16), dim3(32, 8)>>>(W, wt, LO_W, 512, 1024);
    tgemm2<0><<<gB2, blk, DS2>>>(xs, LO_X, wt, nullptr,
                                 s0, LO_STATE, BT, 512, 0, 1);

    // main: h0 fold (3-pass, needs only PT(0)) + level 1 (needs only PT(0))
    tgemm<2><<<dim3(32, 1), blk, DS32>>>(h0s, LO_H0, PT_(0), LO_P,
                                         s0, s0, LO_STATE,
                                         32, 1024, 3);
    tgemm2<1><<<gB2, blk, DS2>>>(s0, LO_STATE, PT_(0), s0, s1, LO_STATE, BT, 1024, 32, 1);

    // ---- join: levels 2+ need PT(1..4) / p32t from s2 ----
    cudaStreamWaitEvent(0, evJoin, 0);

    // ---- levels 2-5 (1-pass), ping-pong s1<->s0 ----
    tgemm2<1><<<gB2, blk, DS2>>>(s1, LO_STATE, PT_(1), s1, s0, LO_STATE, BT, 1024,  64, 1);
    tgemm2<1><<<gB2, blk, DS2>>>(s0, LO_STATE, PT_(2), s0, s1, LO_STATE, BT, 1024, 128, 1);
    tgemm2<1><<<gB2, blk, DS2>>>(s1, LO_STATE, PT_(3), s1, s0, LO_STATE, BT, 1024, 256, 1);
    tgemm2<1><<<gB2, blk, DS2>>>(s0, LO_STATE, PT_(4), s0, s1, LO_STATE, BT, 1024, 512, 1);

    // ---- persistent flag-chained scan (31 chunks + chunk-0 copy, 1 launch) ----
    tscan<<<256, blk, DS32>>>(p32t, s1, out);

    (void)in_sizes; (void)n_in; (void)out_size;
}

// round 17
// speedup vs baseline: 1.0842x; 1.0842x over previous
#include <cuda_runtime.h>
#include <cuda_fp16.h>
#include <cstdint>

// Linear RNN h_t = x_t@W + h_{t-1}@R via log-doubling scan, HMMA mma.sync fp16
// hi/lo-split core, fp32 accum. Power chain on forked stream (3-pass, hidden).
// R16: level 5 FUSED into the persistent scan: each chunk does a serial-free
// GEMM (s0[r-512]@R^16) before its acquire-wait, then the serial chain GEMM
// (s1_{c-1}@R^32), then v = acc + s0_c. Removes one full 32768-row level.

#define UD 1024
#define BT 32768

// hi/lo contiguous: lo part lives at a fixed element offset from hi
#define LO_STATE 33554432
#define LO_X     16777216
#define LO_H0    32768
#define LO_P     1048576
#define LO_W     524288

__device__ __half g_s0[67108864];     // state ping [hi|lo]
__device__ __half g_s1[67108864];     // state pong [hi|lo]
__device__ __half g_x [33554432];     // x time-major [hi|lo]
__device__ __half g_h0[65536];        // h0 [hi|lo]
__device__ __half g_wt[1048576];      // W^T K-major [hi|lo]
__device__ __half g_p [5][2097152];   // R^(2^l) row-major [hi|lo]
__device__ __half g_pt[5][2097152];   // (R^T)^(2^l) K-major [hi|lo]
__device__ __half g_p32t[2097152];    // (R^T)^32 for the scan [hi|lo]
__device__ unsigned int g_done[256];  // [chunk c][rowTile] completion counters

// ---------------- helpers ----------------
__device__ __forceinline__ uint32_t smem_u32(const void* p) {
    uint32_t a;
    asm("{ .reg .u64 t; cvta.to.shared.u64 t, %1; cvt.u32.u64 %0, t; }"
        : "=r"(a) : "l"(p));
    return a;
}
__device__ __forceinline__ void cpa16(uint32_t d, const void* s) {
    asm volatile("cp.async.cg.shared.global [%0], [%1], 16;" :: "r"(d), "l"(s) : "memory");
}
#define CPA_COMMIT() asm volatile("cp.async.commit_group;" ::: "memory")

__device__ __forceinline__ uint32_t pk(__half a, __half b) {
    return (uint32_t)__half_as_ushort(a) | ((uint32_t)__half_as_ushort(b) << 16);
}
__device__ __forceinline__ void split4(float4 v, uint2& h, uint2& l) {
    __half h0 = __float2half(v.x), h1 = __float2half(v.y);
    __half h2 = __float2half(v.z), h3 = __float2half(v.w);
    __half l0 = __float2half(v.x - __half2float(h0));
    __half l1 = __float2half(v.y - __half2float(h1));
    __half l2 = __float2half(v.z - __half2float(h2));
    __half l3 = __float2half(v.w - __half2float(h3));
    h.x = pk(h0, h1); h.y = pk(h2, h3);
    l.x = pk(l0, l1); l.y = pk(l2, l3);
}

#define LDSM4(r0, r1, r2, r3, ad) \
    asm volatile("ldmatrix.sync.aligned.m8n8.x4.shared.b16 {%0,%1,%2,%3}, [%4];" \
        : "=r"(r0), "=r"(r1), "=r"(r2), "=r"(r3) : "r"(ad))

#define MMA16816(acc, a, b) \
    asm volatile( \
        "mma.sync.aligned.m16n8k16.row.col.f32.f16.f16.f32 " \
        "{%0,%1,%2,%3}, {%4,%5,%6,%7}, {%8,%9}, {%0,%1,%2,%3};" \
        : "+f"((acc)[0]), "+f"((acc)[1]), "+f"((acc)[2]), "+f"((acc)[3]) \
        : "r"((a)[0]), "r"((a)[1]), "r"((a)[2]), "r"((a)[3]), \
          "r"((b)[0]), "r"((b)[1]))

// ======================= TM=128 / TN=32 GEMM (powers, h0 fold) ===============
// C[m,n] = sum_k A[m,k]*Bt[n,k] (Bt K-major [N,K]); nPass in {1,2,3}:
// pass 0: Ah*Bh, pass 1: Al*Bh, pass 2: Ah*Bl (fp32 accum).
// MODE 0: C = A@B     MODE 2: C[r] = S[r] + A[r]@B
template<int MODE>
__global__ void __launch_bounds__(256, 2) tgemm(
    const __half* __restrict__ A, int loA,
    const __half* __restrict__ Bm, int loB,
    const __half* __restrict__ S,
    __half* __restrict__ C, int loSC,
    int M, int Kd, int nPass)
{
    constexpr int TN = 32;
    constexpr int ABYTES = 128 * 128;
    constexpr int STG    = ABYTES + TN * 128;
    extern __shared__ char smem_[];

    const int tid  = threadIdx.x;
    const int wid  = tid >> 5, lane = tid & 31;
    const int rowTile = blockIdx.y * 128;
    const int colBase = blockIdx.x * TN;
    const int wr = wid >> 1, wc = wid & 1;
    constexpr int NN = 2;
    const int wcBase = wc * 16;

    const uint32_t sb = smem_u32(smem_);
    const int nk   = Kd >> 6;
    const int nSeg = nPass * nk;

    const __half* baseA[4];
    uint32_t aoffs[4];
    #pragma unroll
    for (int i = 0; i < 4; i++) {
        int t = tid + i * 256;
        int row = t >> 3, ch = t & 7;
        int r = rowTile + row;
        int ar = r < 0 ? 0 : (r > M - 1 ? M - 1 : r);
        baseA[i] = A + (size_t)ar * Kd + ch * 8;
        aoffs[i] = row * 128 + ((ch ^ (row & 7)) << 4);
    }
    const __half* baseB;
    uint32_t boffs;
    {
        int row = tid >> 3, ch = tid & 7;
        baseB = Bm + (size_t)(colBase + row) * Kd + ch * 8;
        boffs = ABYTES + row * 128 + ((ch ^ (row & 7)) << 4);
    }

    auto load_stage = [&](int buf, int seg) {
        int phase = (seg >= nk) + (seg >= 2 * nk);
        int koff  = (seg - phase * nk) * 64;
        int dA = koff + ((phase == 1) ? loA : 0);
        int dB = koff + ((phase == 2) ? loB : 0);
        const uint32_t stb = sb + buf * STG;
        #pragma unroll
        for (int i = 0; i < 4; i++) cpa16(stb + aoffs[i], baseA[i] + dA);
        cpa16(stb + boffs, baseB + dB);
    };

    const int sw = lane & 7;
    const uint32_t arow0 = (uint32_t)((wr * 32 + (lane & 15)) * 128);
    const int aunit = (lane >> 4);
    const uint32_t brow0 = (uint32_t)((wcBase + ((lane >> 4) << 3) + (lane & 7)) * 128);
    const int bunit = (lane >> 3) & 1;

    float acc[2][NN][4] = {};

    load_stage(0, 0); CPA_COMMIT();
    if (nSeg > 1) load_stage(1, 1);
    CPA_COMMIT();

    for (int s = 0; s < nSeg; s++) {
        asm volatile("cp.async.wait_group 1;" ::: "memory");
        __syncthreads();
        if (s + 2 < nSeg) load_stage((s + 2) % 3, s + 2);
        CPA_COMMIT();
        const uint32_t abase = sb + (s % 3) * STG;
        #pragma unroll
        for (int k16 = 0; k16 < 4; k16++) {
            uint32_t a[2][4], b[NN][2];
            #pragma unroll
            for (int mi = 0; mi < 2; mi++) {
                uint32_t ad = abase + arow0 + mi * (16 * 128)
                            + (((k16 * 2 + aunit) ^ sw) << 4);
                LDSM4(a[mi][0], a[mi][1], a[mi][2], a[mi][3], ad);
            }
            {
                uint32_t bd = abase + ABYTES + brow0
                            + (((k16 * 2 + bunit) ^ sw) << 4);
                LDSM4(b[0][0], b[0][1], b[1][0], b[1][1], bd);
            }
            #pragma unroll
            for (int mi = 0; mi < 2; mi++)
                #pragma unroll
                for (int nj = 0; nj < NN; nj++)
                    MMA16816(acc[mi][nj], a[mi], b[nj]);
        }
    }

    #pragma unroll
    for (int mi = 0; mi < 2; mi++) {
        #pragma unroll
        for (int half = 0; half < 2; half++) {
            int rr = rowTile + wr * 32 + mi * 16 + half * 8 + (lane >> 2);
            if (rr >= M) continue;
            const size_t rb = (size_t)rr * UD;
            #pragma unroll
            for (int nj = 0; nj < NN; nj++) {
                int col = colBase + wcBase + nj * 8 + (lane & 3) * 2;
                float v0 = acc[mi][nj][half * 2];
                float v1 = acc[mi][nj][half * 2 + 1];
                if (MODE == 2) {
                    __half2 sh2 = *(const __half2*)(S + rb + col);
                    __half2 sl2 = *(const __half2*)(S + loSC + rb + col);
                    float2 fh = __half22float2(sh2);
                    float2 fl = __half22float2(sl2);
                    v0 += fh.x + fl.x;
                    v1 += fh.y + fl.y;
                }
                __half h0_ = __float2half(v0), h1_ = __float2half(v1);
                __half l0_ = __float2half(v0 - __half2float(h0_));
                __half l1_ = __float2half(v1 - __half2float(h1_));
                *(uint32_t*)(C + rb + col)        = pk(h0_, h1_);
                *(uint32_t*)(C + loSC + rb + col) = pk(l0_, l1_);
            }
        }
    }
}

// ======================= TM=256 / TN=128 GEMM (xW + doubling levels) =========
// nPass in {1,2}: pass 0: Ah*Bh, pass 1: Al*Bh (B hi-only).
// MODE 0: C = A@B
// MODE 1: C[r] = S[r] + (r>=shift ? A[r-shift]@B : 0)
template<int MODE>
__global__ void __launch_bounds__(256, 1) tgemm2(
    const __half* __restrict__ A, int loA,
    const __half* __restrict__ Bm,
    const __half* __restrict__ S,
    __half* __restrict__ C, int loSC,
    int M, int Kd, int shift, int nPass)
{
    constexpr int ABYTES = 256 * 128;          // 256 rows x 64 fp16
    constexpr int BBYTES = 128 * 128;
    constexpr int STG    = ABYTES + BBYTES;
    extern __shared__ char smem_[];

    const int tid  = threadIdx.x;
    const int wid  = tid >> 5, lane = tid & 31;
    const int rowTile = blockIdx.y * 256;
    const int colBase = blockIdx.x * 128;
    const int wr = wid >> 1, wc = wid & 1;     // 4x2 warp grid: 64 rows x 64 cols

    const uint32_t sb = smem_u32(smem_);
    const int nk   = Kd >> 6;
    const int nSeg = nPass * nk;

    const __half* baseA[8];
    uint32_t aoffs[8];
    #pragma unroll
    for (int i = 0; i < 8; i++) {
        int t = tid + i * 256;
        int row = t >> 3, ch = t & 7;
        int r = rowTile + row;
        int ar = (MODE == 1) ? r - shift : r;
        ar = ar < 0 ? 0 : (ar > M - 1 ? M - 1 : ar);
        baseA[i] = A + (size_t)ar * Kd + ch * 8;
        aoffs[i] = row * 128 + ((ch ^ (row & 7)) << 4);
    }
    const __half* baseB[4];
    uint32_t boffs[4];
    #pragma unroll
    for (int i = 0; i < 4; i++) {
        int t = tid + i * 256;
        int row = t >> 3, ch = t & 7;
        baseB[i] = Bm + (size_t)(colBase + row) * Kd + ch * 8;
        boffs[i] = ABYTES + row * 128 + ((ch ^ (row & 7)) << 4);
    }

    auto load_stage = [&](int buf, int seg) {
        int phase = (seg >= nk) ? 1 : 0;
        int koff  = (seg - phase * nk) * 64;
        int dA = koff + (phase ? loA : 0);
        const uint32_t stb = sb + buf * STG;
        #pragma unroll
        for (int i = 0; i < 8; i++) cpa16(stb + aoffs[i], baseA[i] + dA);
        #pragma unroll
        for (int i = 0; i < 4; i++) cpa16(stb + boffs[i], baseB[i] + koff);
    };

    const int sw = lane & 7;
    const uint32_t arow0 = (uint32_t)((wr * 64 + (lane & 15)) * 128);
    const int aunit = (lane >> 4);
    const uint32_t brow0 = (uint32_t)((wc * 64 + ((lane >> 4) << 3) + (lane & 7)) * 128);
    const int bunit = (lane >> 3) & 1;

    float acc[4][8][4] = {};

    load_stage(0, 0); CPA_COMMIT();
    if (nSeg > 1) load_stage(1, 1);
    CPA_COMMIT();

    for (int s = 0; s < nSeg; s++) {
        asm volatile("cp.async.wait_group 1;" ::: "memory");
        __syncthreads();
        if (s + 2 < nSeg) load_stage((s + 2) % 3, s + 2);
        CPA_COMMIT();
        const uint32_t abase = sb + (s % 3) * STG;
        #pragma unroll
        for (int k16 = 0; k16 < 4; k16++) {
            uint32_t a[4][4], b[8][2];
            #pragma unroll
            for (int mi = 0; mi < 4; mi++) {
                uint32_t ad = abase + arow0 + mi * (16 * 128)
                            + (((k16 * 2 + aunit) ^ sw) << 4);
                LDSM4(a[mi][0], a[mi][1], a[mi][2], a[mi][3], ad);
            }
            #pragma unroll
            for (int bj = 0; bj < 4; bj++) {
                uint32_t bd = abase + ABYTES + brow0 + bj * (16 * 128)
                            + (((k16 * 2 + bunit) ^ sw) << 4);
                LDSM4(b[2 * bj][0], b[2 * bj][1], b[2 * bj + 1][0], b[2 * bj + 1][1], bd);
            }
            #pragma unroll
            for (int mi = 0; mi < 4; mi++)
                #pragma unroll
                for (int nj = 0; nj < 8; nj++)
                    MMA16816(acc[mi][nj], a[mi], b[nj]);
        }
    }

    #pragma unroll
    for (int mi = 0; mi < 4; mi++) {
        #pragma unroll
        for (int half = 0; half < 2; half++) {
            int rr = rowTile + wr * 64 + mi * 16 + half * 8 + (lane >> 2);
            if (rr >= M) continue;
            const bool live = (MODE != 1) || (rr >= shift);
            const size_t rb = (size_t)rr * UD;
            #pragma unroll
            for (int nj = 0; nj < 8; nj++) {
                int col = colBase + wc * 64 + nj * 8 + (lane & 3) * 2;
                float v0 = acc[mi][nj][half * 2];
                float v1 = acc[mi][nj][half * 2 + 1];
                if (MODE == 1) {
                    __half2 sh2 = *(const __half2*)(S + rb + col);
                    __half2 sl2 = *(const __half2*)(S + loSC + rb + col);
                    float2 fh = __half22float2(sh2);
                    float2 fl = __half22float2(sl2);
                    v0 = fh.x + fl.x + (live ? v0 : 0.f);
                    v1 = fh.y + fl.y + (live ? v1 : 0.f);
                }
                __half h0_ = __float2half(v0), h1_ = __float2half(v1);
                __half l0_ = __float2half(v0 - __half2float(h0_));
                __half l1_ = __float2half(v1 - __half2float(h1_));
                *(uint32_t*)(C + rb + col)        = pk(h0_, h1_);
                *(uint32_t*)(C + loSC + rb + col) = pk(l0_, l1_);
            }
        }
    }
}

// ================= persistent fused level5 + flag-chained scan ===============
// Per chunk c (0..31), per CTA (rt 0..7, col 0..31):
//   acc  = s0[r-512] @ R^16   (GEMM1, no serial dep; skipped for c=0 stripes<512)
//   wait flag(c-1, rt) if c>=1
//   acc += s1[c-1]  @ R^32    (GEMM2, serial chain)
//   v = acc + s0_c[r]; write s1_c (fp16 hi/lo) + OUT (fp32, transposed); flag(c)
// 256 CTAs, all resident (occupancy 2). Same deadlock-free protocol as R11.
__global__ void __launch_bounds__(256, 2) tscan(
    const __half* __restrict__ B32,  // (R^T)^32 K-major [hi|lo]
    const __half* __restrict__ B16,  // (R^T)^16 K-major [hi|lo] = PT(4)
    const __half* __restrict__ S0,   // post-L4 state (hi; lo at +LO_STATE)
    __half* __restrict__ S1,         // output state
    float* __restrict__ OUT)
{
    constexpr int TN = 32;
    constexpr int ABYTES = 128 * 128;
    constexpr int STG    = ABYTES + TN * 128;
    extern __shared__ char smem_[];

    const int tid  = threadIdx.x;
    const int wid  = tid >> 5, lane = tid & 31;
    const int rtIdx = blockIdx.x >> 5;           // 0..7
    const int rowTile = rtIdx * 128;
    const int colBase = (blockIdx.x & 31) * TN;
    const int wr = wid >> 1, wc = wid & 1;
    constexpr int NN = 2;
    const int wcBase = wc * 16;
    const uint32_t sb = smem_u32(smem_);

    // ---- constant addressing ----
    uint32_t aoffs[4]; int arowL[4], achL[4];
    #pragma unroll
    for (int i = 0; i < 4; i++) {
        int t = tid + i * 256;
        int row = t >> 3, ch = t & 7;
        arowL[i] = rowTile + row;                // chunk-relative row
        achL[i]  = ch * 8;
        aoffs[i] = row * 128 + ((ch ^ (row & 7)) << 4);
    }
    const size_t bRowOff = (size_t)(colBase + (tid >> 3)) * UD + (tid & 7) * 8;
    const uint32_t boffs = ABYTES + (tid >> 3) * 128
                         + (((tid & 7) ^ ((tid >> 3) & 7)) << 4);

    const int sw = lane & 7;
    const uint32_t arow0 = (uint32_t)((wr * 32 + (lane & 15)) * 128);
    const int aunit = (lane >> 4);
    const uint32_t brow0 = (uint32_t)((wcBase + ((lane >> 4) << 3) + (lane & 7)) * 128);
    const int bunit = (lane >> 3) & 1;

    float acc[2][NN][4];

    // pipelined 16-segment GEMM accumulation: acc += Ab[rows] @ Bb
    auto run_gemm = [&](const __half* Ab, const __half* Bb) {
        auto load_stage = [&](int buf, int seg) {
            int koff = seg * 64;
            const uint32_t stb = sb + buf * STG;
            #pragma unroll
            for (int i = 0; i < 4; i++)
                cpa16(stb + aoffs[i], Ab + (size_t)arowL[i] * UD + achL[i] + koff);
            cpa16(stb + boffs, Bb + bRowOff + koff);
        };
        load_stage(0, 0); CPA_COMMIT();
        load_stage(1, 1); CPA_COMMIT();
        for (int seg = 0; seg < 16; seg++) {
            asm volatile("cp.async.wait_group 1;" ::: "memory");
            __syncthreads();
            if (seg + 2 < 16) load_stage((seg + 2) % 3, seg + 2);
            CPA_COMMIT();
            const uint32_t abase = sb + (seg % 3) * STG;
            #pragma unroll
            for (int k16 = 0; k16 < 4; k16++) {
                uint32_t a[2][4], b[NN][2];
                #pragma unroll
                for (int mi = 0; mi < 2; mi++) {
                    uint32_t ad = abase + arow0 + mi * (16 * 128)
                                + (((k16 * 2 + aunit) ^ sw) << 4);
                    LDSM4(a[mi][0], a[mi][1], a[mi][2], a[mi][3], ad);
                }
                {
                    uint32_t bd = abase + ABYTES + brow0
                                + (((k16 * 2 + bunit) ^ sw) << 4);
                    LDSM4(b[0][0], b[0][1], b[1][0], b[1][1], bd);
                }
                #pragma unroll
                for (int mi = 0; mi < 2; mi++)
                    #pragma unroll
                    for (int nj = 0; nj < NN; nj++)
                        MMA16816(acc[mi][nj], a[mi], b[nj]);
            }
        }
        __syncthreads();   // all warps done with smem before any reuse
    };

    for (int c = 0; c < 32; c++) {
        #pragma unroll
        for (int mi = 0; mi < 2; mi++)
            #pragma unroll
            for (int nj = 0; nj < NN; nj++)
                #pragma unroll
                for (int q = 0; q < 4; q++) acc[mi][nj][q] = 0.f;

        // GEMM1 (level 5, no serial dep): rows r-512 of s0; tile-uniform pred
        if (c * 1024 + rowTile >= 512)
            run_gemm(S0 + ((size_t)c * 1024 - 512) * UD, B16);

        // acquire scan chain
        if (c >= 1) {
            if (tid == 0) {
                while (((volatile unsigned int*)g_done)[(c - 1) * 8 + rtIdx] < 32u) {}
                __threadfence();
            }
            __syncthreads();
            // GEMM2 (serial): previous chunk's final state @ R^32
            run_gemm(S1 + (size_t)(c - 1) * 1048576, B32);
        }

        // epilogue: v = acc + s0_c (hi+lo); write s1_c + OUT transposed
        const int rowOff = c * 1024;
        const size_t cb = (size_t)c * 1048576;
        #pragma unroll
        for (int mi = 0; mi < 2; mi++) {
            #pragma unroll
            for (int half = 0; half < 2; half++) {
                int rr = rowTile + wr * 32 + mi * 16 + half * 8 + (lane >> 2);
                const size_t rb = cb + (size_t)rr * UD;
                int g = rowOff + rr;
                float* op = OUT + (size_t)((g & 31) * 1024 + (g >> 5)) * UD;
                #pragma unroll
                for (int nj = 0; nj < NN; nj++) {
                    int col = colBase + wcBase + nj * 8 + (lane & 3) * 2;
                    float v0 = acc[mi][nj][half * 2];
                    float v1 = acc[mi][nj][half * 2 + 1];
                    __half2 sh2 = *(const __half2*)(S0 + rb + col);
                    __half2 sl2 = *(const __half2*)(S0 + LO_STATE + rb + col);
                    float2 fh = __half22float2(sh2);
                    float2 fl = __half22float2(sl2);
                    v0 += fh.x + fl.x;
                    v1 += fh.y + fl.y;
                    __half h0_ = __float2half(v0), h1_ = __float2half(v1);
                    __half l0_ = __float2half(v0 - __half2float(h0_));
                    __half l1_ = __float2half(v1 - __half2float(h1_));
                    *(uint32_t*)(S1 + rb + col)            = pk(h0_, h1_);
                    *(uint32_t*)(S1 + LO_STATE + rb + col) = pk(l0_, l1_);
                    op[col] = v0; op[col + 1] = v1;
                }
            }
        }

        // release
        __threadfence();
        __syncthreads();
        if (tid == 0) atomicAdd(&g_done[c * 8 + rtIdx], 1u);
    }
}

__global__ void zero_done() { g_done[threadIdx.x] = 0u; }

// ======================= pre kernels =======================
__global__ void split_x(const float* __restrict__ x, __half* __restrict__ o)
{
    int id = blockIdx.x * 256 + threadIdx.x;
    int r = id >> 7;                                  // time-major row t*32+b
    int c = (id & 127) << 2;
    int b = r & 31, t = r >> 5;
    float4 vv = *(const float4*)(x + (size_t)(b * 1024 + t) * 512 + c);
    uint2 h, l; split4(vv, h, l);
    *(uint2*)(o + (size_t)r * 512 + c) = h;
    *(uint2*)(o + LO_X + (size_t)r * 512 + c) = l;
}

__global__ void split_plain(const float* __restrict__ in,
                            __half* __restrict__ o, int loOff)
{
    int id = blockIdx.x * 256 + threadIdx.x;
    float4 vv = *(const float4*)(in + (size_t)id * 4);
    uint2 h, l; split4(vv, h, l);
    *(uint2*)(o + (size_t)id * 4) = h;
    *(uint2*)(o + loOff + (size_t)id * 4) = l;
}

__global__ void tsplit(const float* __restrict__ in,
                       __half* __restrict__ o, int loOff, int K, int N)
{
    __shared__ float tile[32][33];
    int nb = blockIdx.x * 32, kb = blockIdx.y * 32;
    int tx = threadIdx.x, ty = threadIdx.y;
    #pragma unroll
    for (int j = 0; j < 32; j += 8)
        tile[ty + j][tx] = in[(size_t)(kb + ty + j) * N + nb + tx];
    __syncthreads();
    #pragma unroll
    for (int j = 0; j < 32; j += 8) {
        float vv = tile[tx][ty + j];
        size_t off = (size_t)(nb + ty + j) * K + kb + tx;
        __half h = __float2half(vv);
        o[off] = h;
        o[loOff + off] = __float2half(vv - __half2float(h));
    }
}

// exact hi/lo fp16 transpose: out[c][r] = in[r][c], 1024x1024, z in {0,1}
__global__ void ttrans(const __half* __restrict__ in, __half* __restrict__ out)
{
    __shared__ __half tile[32][33];
    const __half* ip = in  + (size_t)blockIdx.z * LO_P;
    __half* op       = out + (size_t)blockIdx.z * LO_P;
    int cb = blockIdx.x * 32, rb = blockIdx.y * 32;
    int tx = threadIdx.x, ty = threadIdx.y;
    #pragma unroll
    for (int j = 0; j < 32; j += 8)
        tile[ty + j][tx] = ip[(size_t)(rb + ty + j) * 1024 + cb + tx];
    __syncthreads();
    #pragma unroll
    for (int j = 0; j < 32; j += 8)
        op[(size_t)(cb + ty + j) * 1024 + rb + tx] = tile[tx][ty + j];
}

// ======================= host =======================
extern "C" void kernel_launch(void* const* d_in, const int* in_sizes, int n_in,
                              void* d_out, int out_size)
{
    const float* x  = (const float*)d_in[0];   // [32,1024,512]
    const float* h0 = (const float*)d_in[1];   // [32,1024]
    const float* W  = (const float*)d_in[2];   // [512,1024]
    const float* R  = (const float*)d_in[3];   // [1024,1024]
    float* out = (float*)d_out;                // [32,1024,1024]

    __half *s0, *s1, *xs, *h0s, *wt, *p, *pt, *p32t;
    cudaGetSymbolAddress((void**)&s0,  g_s0);
    cudaGetSymbolAddress((void**)&s1,  g_s1);
    cudaGetSymbolAddress((void**)&xs,  g_x);
    cudaGetSymbolAddress((void**)&h0s, g_h0);
    cudaGetSymbolAddress((void**)&wt,  g_wt);
    cudaGetSymbolAddress((void**)&p,   g_p);
    cudaGetSymbolAddress((void**)&pt,  g_pt);
    cudaGetSymbolAddress((void**)&p32t, g_p32t);

    auto P_  = [&](int i) { return p  + (size_t)i * 2097152; };
    auto PT_ = [&](int i) { return pt + (size_t)i * 2097152; };

    constexpr int DS32 = 3 * (128 + 32) * 128;    // 61440
    constexpr int DS2  = 3 * (256 + 128) * 128;   // 147456
    cudaFuncSetAttribute(tgemm<0>,  cudaFuncAttributeMaxDynamicSharedMemorySize, DS32);
    cudaFuncSetAttribute(tgemm<2>,  cudaFuncAttributeMaxDynamicSharedMemorySize, DS32);
    cudaFuncSetAttribute(tgemm2<0>, cudaFuncAttributeMaxDynamicSharedMemorySize, DS2);
    cudaFuncSetAttribute(tgemm2<1>, cudaFuncAttributeMaxDynamicSharedMemorySize, DS2);
    cudaFuncSetAttribute(tscan,     cudaFuncAttributeMaxDynamicSharedMemorySize, DS32);

    // forked stream + events (host-side objects only; fresh each call)
    cudaStream_t s2;
    cudaEvent_t evFork, evJoin;
    cudaStreamCreateWithFlags(&s2, cudaStreamNonBlocking);
    cudaEventCreateWithFlags(&evFork, cudaEventDisableTiming);
    cudaEventCreateWithFlags(&evJoin, cudaEventDisableTiming);

    dim3 blk(256);
    dim3 gPow(32, 8);    // 1024-row GEMMs, TM=128/TN=32
    dim3 gB2(8, 128);    // 32768-row GEMMs, TM=256/TN=128
    dim3 gT(32, 32, 2);  // hi/lo transpose
    dim3 bT(32, 8);

    // ---- shared prerequisites (main stream) ----
    split_plain<<<32, 256>>>(h0, h0s, LO_H0);
    split_plain<<<1024, 256>>>(R, P_(0), LO_P);
    tsplit<<<dim3(32, 32), dim3(32, 8)>>>(R, PT_(0), LO_P, 1024, 1024);

    // ---- fork: power chain (3-pass, fully hidden) on s2 ----
    cudaEventRecord(evFork, 0);
    cudaStreamWaitEvent(s2, evFork, 0);

    zero_done<<<1, 256, 0, s2>>>();
    for (int lv = 1; lv < 5; lv++) {
        tgemm<0><<<gPow, blk, DS32, s2>>>(P_(lv-1), LO_P, PT_(lv-1), LO_P,
                                          nullptr, P_(lv), LO_P,
                                          1024, 1024, 3);
        ttrans<<<gT, bT, 0, s2>>>(P_(lv), PT_(lv));
    }
    tgemm<0><<<gPow, blk, DS32, s2>>>(PT_(4), LO_P, P_(4), LO_P,
                                      nullptr, p32t, LO_P,
                                      1024, 1024, 3);
    cudaEventRecord(evJoin, s2);

    // main: x split + W split + b0 = x @ W (1-pass)
    split_x<<<16384, 256>>>(x, xs);
    tsplit<<<dim3(32, 16), dim3(32, 8)>>>(W, wt, LO_W, 512, 1024);
    tgemm2<0><<<gB2, blk, DS2>>>(xs, LO_X, wt, nullptr,
                                 s0, LO_STATE, BT, 512, 0, 1);

    // main: h0 fold (3-pass) + level 1 (both need only PT(0))
    tgemm<2><<<dim3(32, 1), blk, DS32>>>(h0s, LO_H0, PT_(0), LO_P,
                                         s0, s0, LO_STATE,
                                         32, 1024, 3);
    tgemm2<1><<<gB2, blk, DS2>>>(s0, LO_STATE, PT_(0), s0, s1, LO_STATE, BT, 1024, 32, 1);

    // ---- join: levels 2-4 need PT(1..3); scan needs PT(4)/p32t ----
    cudaStreamWaitEvent(0, evJoin, 0);

    // ---- levels 2-4 (1-pass): s1 -> s0 -> s1 -> s0 (final pre-scan in s0) ----
    tgemm2<1><<<gB2, blk, DS2>>>(s1, LO_STATE, PT_(1), s1, s0, LO_STATE, BT, 1024,  64, 1);
    tgemm2<1><<<gB2, blk, DS2>>>(s0, LO_STATE, PT_(2), s0, s1, LO_STATE, BT, 1024, 128, 1);
    tgemm2<1><<<gB2, blk, DS2>>>(s1, LO_STATE, PT_(3), s1, s0, LO_STATE, BT, 1024, 256, 1);

    // ---- persistent fused L5+scan (32 chunks, 1 launch) ----
    tscan<<<256, blk, DS32>>>(p32t, PT_(4), s0, s1, out);

    (void)in_sizes; (void)n_in; (void)out_size;
}